// round 7
// baseline (speedup 1.0000x reference)
#include <cuda_runtime.h>
#include <cuda_bf16.h>
#include <math.h>
#include <stdint.h>

// Problem constants
#define B_    256
#define T_    192
#define F_    8
#define E0_   32
#define E1_   16
#define DINP  64          // padded input dim (real 56)
#define H_    512
#define G4_   2048
#define BT_   (B_ * T_)   // 49152
#define KC    32

// Scan smem: Bs [64][520] bf16 + As [64][520] bf16 + 4 mbarriers
#define NROW  520
#define SC_TILE_BYTES (64 * NROW * 2)
#define SC_SMEM (2 * SC_TILE_BYTES + 64)

// ---------------- scratch (static device arrays; no allocation) ----------------
__device__ float g_x  [(size_t)BT_ * DINP];            // padded concat input (fp32)
__device__ float g_wk1p[DINP * G4_];                   // padded Wk1
__device__ __nv_bfloat16 g_xz [(size_t)BT_ * G4_];     // input projection (+bias), bf16
__device__ __nv_bfloat16 g_hs1[(size_t)BT_ * H_];      // layer1 hidden outputs (bf16)
__device__ __nv_bfloat16 g_hs2[(size_t)BT_ * H_];      // layer2 hidden outputs (bf16)
__device__ unsigned g_ctr[8];

// ---------------- helpers ----------------
__device__ __forceinline__ unsigned f2tf(float x) {
    unsigned r;
    asm("cvt.rna.tf32.f32 %0, %1;" : "=r"(r) : "f"(x));
    return r;
}

__device__ __forceinline__ void mma8(float* c,
                                     unsigned a0, unsigned a1, unsigned a2, unsigned a3,
                                     unsigned b0, unsigned b1) {
    asm volatile(
        "mma.sync.aligned.m16n8k8.row.col.f32.tf32.tf32.f32 "
        "{%0,%1,%2,%3},{%4,%5,%6,%7},{%8,%9},{%0,%1,%2,%3};\n"
        : "+f"(c[0]), "+f"(c[1]), "+f"(c[2]), "+f"(c[3])
        : "r"(a0), "r"(a1), "r"(a2), "r"(a3), "r"(b0), "r"(b1));
}

__device__ __forceinline__ void mma16bf(float* c,
                                        unsigned a0, unsigned a1, unsigned a2, unsigned a3,
                                        unsigned b0, unsigned b1) {
    asm volatile(
        "mma.sync.aligned.m16n8k16.row.col.f32.bf16.bf16.f32 "
        "{%0,%1,%2,%3},{%4,%5,%6,%7},{%8,%9},{%0,%1,%2,%3};\n"
        : "+f"(c[0]), "+f"(c[1]), "+f"(c[2]), "+f"(c[3])
        : "r"(a0), "r"(a1), "r"(a2), "r"(a3), "r"(b0), "r"(b1));
}

__device__ __forceinline__ void ldsm4(unsigned& r0, unsigned& r1, unsigned& r2, unsigned& r3,
                                      const void* p) {
    unsigned a = (unsigned)__cvta_generic_to_shared(p);
    asm volatile("ldmatrix.sync.aligned.m8n8.x4.shared.b16 {%0,%1,%2,%3}, [%4];"
                 : "=r"(r0), "=r"(r1), "=r"(r2), "=r"(r3) : "r"(a));
}

// fast sigmoid/tanh via MUFU.EX2 path (precision ~1e-6, negligible vs bf16 noise)
__device__ __forceinline__ float sigm(float x) {
    float e = __expf(-x);
    return __fdividef(1.0f, 1.0f + e);
}
__device__ __forceinline__ float tanhfast(float x) {
    float e = __expf(-2.0f * x);
    return __fdividef(2.0f, 1.0f + e) - 1.0f;
}

__device__ __forceinline__ void cpa16(void* dst, const void* src) {
    unsigned d = (unsigned)__cvta_generic_to_shared(dst);
    asm volatile("cp.async.ca.shared.global [%0], [%1], 16;\n" :: "r"(d), "l"(src));
}
#define CP_COMMIT asm volatile("cp.async.commit_group;\n")
#define CP_WAIT0  asm volatile("cp.async.wait_group 0;\n")
#define CP_WAIT1  asm volatile("cp.async.wait_group 1;\n")

__device__ __forceinline__ void mbar_init(uint32_t mbar, unsigned cnt) {
    asm volatile("mbarrier.init.shared.b64 [%0], %1;" :: "r"(mbar), "r"(cnt) : "memory");
}
__device__ __forceinline__ void mbar_expect_tx(uint32_t mbar, unsigned bytes) {
    asm volatile("mbarrier.arrive.expect_tx.shared.b64 _, [%0], %1;"
                 :: "r"(mbar), "r"(bytes) : "memory");
}
__device__ __forceinline__ void bulk_cp(uint32_t dst_smem, const void* src,
                                        unsigned bytes, uint32_t mbar) {
    asm volatile("cp.async.bulk.shared::cluster.global.mbarrier::complete_tx::bytes "
                 "[%0], [%1], %2, [%3];"
                 :: "r"(dst_smem), "l"(src), "r"(bytes), "r"(mbar) : "memory");
}
__device__ __forceinline__ void mbar_wait(uint32_t mbar, uint32_t parity) {
    uint32_t done;
    asm volatile("{\n\t.reg .pred p;\n\t"
                 "mbarrier.try_wait.parity.acquire.cta.shared::cta.b64 p, [%1], %2;\n\t"
                 "selp.b32 %0, 1, 0, p;\n\t}"
                 : "=r"(done) : "r"(mbar), "r"(parity) : "memory");
    if (!done) {
        asm volatile("{\n\t.reg .pred P1;\n\t"
                     "WAIT_LOOP_%=:\n\t"
                     "mbarrier.try_wait.parity.acquire.cta.shared::cta.b64 P1, [%0], %1, 0x989680;\n\t"
                     "@P1 bra.uni WAIT_DONE_%=;\n\t"
                     "bra.uni WAIT_LOOP_%=;\n\t"
                     "WAIT_DONE_%=:\n\t}"
                     :: "r"(mbar), "r"(parity) : "memory");
    }
}

// ---------------- tiny kernels ----------------
__global__ void k_init() {
    if (threadIdx.x < 8) g_ctr[threadIdx.x] = 0u;
}

__global__ void k_build_x(const float* __restrict__ xc,
                          const int* __restrict__ c0, const int* __restrict__ c1,
                          const float* __restrict__ e0, const float* __restrict__ e1) {
    int i = blockIdx.x * blockDim.x + threadIdx.x;
    if (i >= BT_ * DINP) return;
    int bt = i >> 6;
    int d  = i & 63;
    float v;
    if (d < F_)                  v = xc[bt * F_ + d];
    else if (d < F_ + E0_)       v = e0[c0[bt] * E0_ + (d - F_)];
    else if (d < F_ + E0_ + E1_) v = e1[c1[bt] * E1_ + (d - F_ - E0_)];
    else                         v = 0.0f;
    g_x[i] = v;
}

__global__ void k_padwk(const float* __restrict__ Wk1) {
    int i = blockIdx.x * blockDim.x + threadIdx.x;
    if (i >= DINP * G4_) return;
    int r = i >> 11, c = i & 2047;
    g_wk1p[i] = (r < 56) ? Wk1[r * G4_ + c] : 0.0f;
}

// ---------------- TF32 GEMM (fp32 A): C[M,2048] = A[M,K] @ W[K,2048] + bias (bf16 out) ----------------
__global__ void __launch_bounds__(256)
k_gemm(const float* __restrict__ A, int lda, int K,
       const float* __restrict__ W, const float* __restrict__ bias,
       __nv_bfloat16* __restrict__ C) {
    __shared__ float As[2][64][36];
    __shared__ float Bs[2][32][72];
    int m0 = blockIdx.x * 64, n0 = blockIdx.y * 64;
    int tid = threadIdx.x;
    int lane = tid & 31, warp = tid >> 5;
    int wm = warp >> 1, wn = warp & 1;
    int g = lane >> 2, tg = lane & 3;

    float acc[4][4];
#pragma unroll
    for (int i = 0; i < 4; i++)
#pragma unroll
        for (int j = 0; j < 4; j++) acc[i][j] = 0.0f;

    int nch = K / KC;
    {
#pragma unroll
        for (int ii = 0; ii < 2; ii++) {
            int idx = tid + 256 * ii;
            int r = idx >> 3, q = idx & 7;
            cpa16(&As[0][r][q * 4], &A[(size_t)(m0 + r) * lda + q * 4]);
        }
#pragma unroll
        for (int ii = 0; ii < 2; ii++) {
            int idx = tid + 256 * ii;
            int k = idx >> 4, q = idx & 15;
            cpa16(&Bs[0][k][q * 4], &W[(size_t)k * G4_ + n0 + q * 4]);
        }
        CP_COMMIT;
    }

    for (int kc = 0; kc < nch; kc++) {
        int b = kc & 1;
        if (kc + 1 < nch) {
            int b2 = b ^ 1;
            int k0 = (kc + 1) * KC;
#pragma unroll
            for (int ii = 0; ii < 2; ii++) {
                int idx = tid + 256 * ii;
                int r = idx >> 3, q = idx & 7;
                cpa16(&As[b2][r][q * 4], &A[(size_t)(m0 + r) * lda + k0 + q * 4]);
            }
#pragma unroll
            for (int ii = 0; ii < 2; ii++) {
                int idx = tid + 256 * ii;
                int k = idx >> 4, q = idx & 15;
                cpa16(&Bs[b2][k][q * 4], &W[(size_t)(k0 + k) * G4_ + n0 + q * 4]);
            }
            CP_COMMIT;
            CP_WAIT1;
        } else {
            CP_WAIT0;
        }
        __syncthreads();
#pragma unroll
        for (int ks = 0; ks < KC; ks += 8) {
            unsigned a0 = f2tf(As[b][wm * 16 + g][ks + tg]);
            unsigned a1 = f2tf(As[b][wm * 16 + g + 8][ks + tg]);
            unsigned a2 = f2tf(As[b][wm * 16 + g][ks + tg + 4]);
            unsigned a3 = f2tf(As[b][wm * 16 + g + 8][ks + tg + 4]);
#pragma unroll
            for (int nt = 0; nt < 4; nt++) {
                unsigned b0 = f2tf(Bs[b][ks + tg][wn * 32 + nt * 8 + g]);
                unsigned b1 = f2tf(Bs[b][ks + tg + 4][wn * 32 + nt * 8 + g]);
                mma8(acc[nt], a0, a1, a2, a3, b0, b1);
            }
        }
        __syncthreads();
    }

    int rl = wm * 16 + g;
#pragma unroll
    for (int nt = 0; nt < 4; nt++) {
        int cl  = wn * 32 + nt * 8 + tg * 2;
        int col = n0 + cl;
        float bb0 = bias[col], bb1 = bias[col + 1];
        size_t o0 = (size_t)(m0 + rl) * G4_ + col;
        size_t o1 = (size_t)(m0 + rl + 8) * G4_ + col;
        __nv_bfloat162 p0 = __floats2bfloat162_rn(acc[nt][0] + bb0, acc[nt][1] + bb1);
        __nv_bfloat162 p1 = __floats2bfloat162_rn(acc[nt][2] + bb0, acc[nt][3] + bb1);
        *reinterpret_cast<__nv_bfloat162*>(C + o0) = p0;
        *reinterpret_cast<__nv_bfloat162*>(C + o1) = p1;
    }
}

// ---------------- TF32 GEMM with bf16 A (layer-2 input projection), K=512, bf16 out ----------------
__global__ void __launch_bounds__(256)
k_gemm_b(const __nv_bfloat16* __restrict__ A,
         const float* __restrict__ W, const float* __restrict__ bias,
         __nv_bfloat16* __restrict__ C) {
    __shared__ __nv_bfloat16 As[2][64][40];
    __shared__ float Bs[2][32][72];
    int m0 = blockIdx.x * 64, n0 = blockIdx.y * 64;
    int tid = threadIdx.x;
    int lane = tid & 31, warp = tid >> 5;
    int wm = warp >> 1, wn = warp & 1;
    int g = lane >> 2, tg = lane & 3;

    float acc[4][4];
#pragma unroll
    for (int i = 0; i < 4; i++)
#pragma unroll
        for (int j = 0; j < 4; j++) acc[i][j] = 0.0f;

    {
        int r = tid >> 2, q = tid & 3;
        cpa16(&As[0][r][q * 8], &A[(size_t)(m0 + r) * H_ + q * 8]);
#pragma unroll
        for (int ii = 0; ii < 2; ii++) {
            int idx = tid + 256 * ii;
            int k = idx >> 4, qq = idx & 15;
            cpa16(&Bs[0][k][qq * 4], &W[(size_t)k * G4_ + n0 + qq * 4]);
        }
        CP_COMMIT;
    }

    for (int kc = 0; kc < 16; kc++) {
        int b = kc & 1;
        if (kc < 15) {
            int b2 = b ^ 1;
            int k0 = (kc + 1) * KC;
            int r = tid >> 2, q = tid & 3;
            cpa16(&As[b2][r][q * 8], &A[(size_t)(m0 + r) * H_ + k0 + q * 8]);
#pragma unroll
            for (int ii = 0; ii < 2; ii++) {
                int idx = tid + 256 * ii;
                int k = idx >> 4, qq = idx & 15;
                cpa16(&Bs[b2][k][qq * 4], &W[(size_t)(k0 + k) * G4_ + n0 + qq * 4]);
            }
            CP_COMMIT;
            CP_WAIT1;
        } else {
            CP_WAIT0;
        }
        __syncthreads();
#pragma unroll
        for (int ks = 0; ks < KC; ks += 8) {
            unsigned a0 = __float_as_uint(__bfloat162float(As[b][wm * 16 + g][ks + tg]));
            unsigned a1 = __float_as_uint(__bfloat162float(As[b][wm * 16 + g + 8][ks + tg]));
            unsigned a2 = __float_as_uint(__bfloat162float(As[b][wm * 16 + g][ks + tg + 4]));
            unsigned a3 = __float_as_uint(__bfloat162float(As[b][wm * 16 + g + 8][ks + tg + 4]));
#pragma unroll
            for (int nt = 0; nt < 4; nt++) {
                unsigned b0 = f2tf(Bs[b][ks + tg][wn * 32 + nt * 8 + g]);
                unsigned b1 = f2tf(Bs[b][ks + tg + 4][wn * 32 + nt * 8 + g]);
                mma8(acc[nt], a0, a1, a2, a3, b0, b1);
            }
        }
        __syncthreads();
    }

    int rl = wm * 16 + g;
#pragma unroll
    for (int nt = 0; nt < 4; nt++) {
        int cl  = wn * 32 + nt * 8 + tg * 2;
        int col = n0 + cl;
        float bb0 = bias[col], bb1 = bias[col + 1];
        size_t o0 = (size_t)(m0 + rl) * G4_ + col;
        size_t o1 = (size_t)(m0 + rl + 8) * G4_ + col;
        __nv_bfloat162 p0 = __floats2bfloat162_rn(acc[nt][0] + bb0, acc[nt][1] + bb1);
        __nv_bfloat162 p1 = __floats2bfloat162_rn(acc[nt][2] + bb0, acc[nt][3] + bb1);
        *reinterpret_cast<__nv_bfloat162*>(C + o0) = p0;
        *reinterpret_cast<__nv_bfloat162*>(C + o1) = p1;
    }
}

// ---------------- persistent bf16 LSTM scan ----------------
// grid (4, 32), 256 threads. CTA: 64 batch rows x 64 z-cols (gate-aligned).
// This round: h staged via cp.async.bulk (64 x 1KB UBLKCP) with 4 per-row-group
// mbarriers; each warp-pair waits only for its own 16 A-rows; no mid-step
// __syncthreads.
__global__ void __launch_bounds__(256)
k_scan(const float* __restrict__ Wr, const __nv_bfloat16* __restrict__ xz,
       __nv_bfloat16* __restrict__ hs, unsigned* __restrict__ ctr) {
    extern __shared__ char smem[];
    __nv_bfloat16* Bsm = reinterpret_cast<__nv_bfloat16*>(smem);
    __nv_bfloat16* Asm = reinterpret_cast<__nv_bfloat16*>(smem + SC_TILE_BYTES);
    uint32_t asm_base = (uint32_t)__cvta_generic_to_shared(Asm);
    uint32_t mbar0 = (uint32_t)__cvta_generic_to_shared(smem + 2 * SC_TILE_BYTES);

    int m0 = blockIdx.x * 64;
    int j0 = blockIdx.y * 16;
    int gidx = blockIdx.x;
    int tid = threadIdx.x;
    int lane = tid & 31, warp = tid >> 5;
    int wm = warp >> 1, wn = warp & 1;
    int g = lane >> 2, tg = lane & 3;

    if (tid < 4) mbar_init(mbar0 + tid * 8, 1);

    // preload Wr slice: row ns holds column gate*512 + j0 + j
    for (int i = tid; i < 64 * 512; i += 256) {
        int ns = i & 63, k = i >> 6;
        int col = ((ns >> 3) & 3) * 512 + j0 + ((ns >> 5) << 3) + (ns & 7);
        Bsm[ns * NROW + k] = __float2bfloat16(Wr[(size_t)k * G4_ + col]);
    }
    __syncthreads();

    // fragment addressing
    int a_row  = wm * 16 + (lane & 7) + ((lane >> 3) & 1) * 8;
    int a_koff = ((lane >> 4) & 1) * 8;
    int b_nl0  = wn * 32 + ((lane >> 4) & 1) * 8 + (lane & 7);
    int b_koff = ((lane >> 3) & 1) * 8;
    int jloc   = wn * 8 + tg * 2;           // this thread's 2 j's
    int r0     = m0 + wm * 16 + g;          // rows r0, r0+8
    uint32_t my_mbar = mbar0 + wm * 8;

    float creg[4] = {0.0f, 0.0f, 0.0f, 0.0f};
    float xf[2][4][2];
    uint32_t phase = 0;

    // prologue: xz for t=0
#pragma unroll
    for (int rr = 0; rr < 2; rr++) {
        const __nv_bfloat16* xp = xz + ((size_t)(r0 + rr * 8) * T_) * G4_ + j0 + jloc;
#pragma unroll
        for (int gate = 0; gate < 4; gate++) {
            __nv_bfloat162 w = *reinterpret_cast<const __nv_bfloat162*>(xp + gate * 512);
            xf[rr][gate][0] = __bfloat162float(w.x);
            xf[rr][gate][1] = __bfloat162float(w.y);
        }
    }

    for (int t = 0; t < T_; t++) {
        // stage h[t-1]: 4 row-groups x 16 bulk copies of 1KB each
        if (t > 0 && (tid & 63) == 0) {
            int grp = tid >> 6;
            uint32_t mb = mbar0 + grp * 8;
            mbar_expect_tx(mb, 16 * 1024);
#pragma unroll
            for (int r = 0; r < 16; r++) {
                int row = grp * 16 + r;
                bulk_cp(asm_base + row * (NROW * 2),
                        &hs[((size_t)(m0 + row) * T_ + (t - 1)) * H_],
                        1024, mb);
            }
        }

        float acc[4][4];
#pragma unroll
        for (int i = 0; i < 4; i++)
#pragma unroll
            for (int j = 0; j < 4; j++) acc[i][j] = 0.0f;

        if (t > 0) {
            mbar_wait(my_mbar, phase);
            phase ^= (t == T_ - 1) ? 0u : 0u;   // phase toggled below once per used step
#pragma unroll 4
            for (int ks = 0; ks < 32; ks++) {
                unsigned a0, a1, a2, a3;
                ldsm4(a0, a1, a2, a3, &Asm[a_row * NROW + ks * 16 + a_koff]);
                unsigned c0, c1, c2, c3;
                ldsm4(c0, c1, c2, c3, &Bsm[b_nl0 * NROW + ks * 16 + b_koff]);
                mma16bf(acc[0], a0, a1, a2, a3, c0, c1);
                mma16bf(acc[1], a0, a1, a2, a3, c2, c3);
                ldsm4(c0, c1, c2, c3, &Bsm[(b_nl0 + 16) * NROW + ks * 16 + b_koff]);
                mma16bf(acc[2], a0, a1, a2, a3, c0, c1);
                mma16bf(acc[3], a0, a1, a2, a3, c2, c3);
            }
            phase ^= 1u;
        }

        // fused cell update, fully in registers
#pragma unroll
        for (int rr = 0; rr < 2; rr++) {
            float hv[2];
#pragma unroll
            for (int jj = 0; jj < 2; jj++) {
                int q = rr * 2 + jj;
                float zi = acc[0][q] + xf[rr][0][jj];
                float zf = acc[1][q] + xf[rr][1][jj];
                float zg = acc[2][q] + xf[rr][2][jj];
                float zo = acc[3][q] + xf[rr][3][jj];
                float iv = sigm(zi);
                float fv = sigm(zf);
                float gv = tanhfast(zg);
                float ov = sigm(zo);
                float cv = fv * creg[q] + iv * gv;
                creg[q] = cv;
                hv[jj] = ov * tanhfast(cv);
            }
            *reinterpret_cast<__nv_bfloat162*>(
                hs + ((size_t)(r0 + rr * 8) * T_ + t) * H_ + j0 + jloc) =
                __floats2bfloat162_rn(hv[0], hv[1]);
        }

        // group barrier: release-scoped arrive by tid0 (after cta barrier)
        __syncthreads();
        if (tid == 0)
            asm volatile("red.release.gpu.global.add.u32 [%0], %1;"
                         :: "l"(ctr + gidx), "r"(1u) : "memory");

        // prefetch next step's xz while others arrive (xf dead after update)
        if (t + 1 < T_) {
#pragma unroll
            for (int rr = 0; rr < 2; rr++) {
                const __nv_bfloat16* xp =
                    xz + ((size_t)(r0 + rr * 8) * T_ + (t + 1)) * G4_ + j0 + jloc;
#pragma unroll
                for (int gate = 0; gate < 4; gate++) {
                    __nv_bfloat162 w = *reinterpret_cast<const __nv_bfloat162*>(xp + gate * 512);
                    xf[rr][gate][0] = __bfloat162float(w.x);
                    xf[rr][gate][1] = __bfloat162float(w.y);
                }
            }
        }

        if (tid == 0) {
            unsigned tgt = 32u * (unsigned)(t + 1);
            unsigned v;
            do {
                asm volatile("ld.acquire.gpu.u32 %0, [%1];" : "=r"(v) : "l"(ctr + gidx));
            } while (v < tgt);
        }
        __syncthreads();
    }
}

// ---------------- output heads: mu, softplus(sigma) (bf16 hs) ----------------
__global__ void k_heads(const __nv_bfloat16* __restrict__ hs,
                        const float* __restrict__ Wmu, const float* __restrict__ bmu,
                        const float* __restrict__ Wsig, const float* __restrict__ bsig,
                        float* __restrict__ out) {
    int wg  = (blockIdx.x * blockDim.x + threadIdx.x) >> 5;
    int lane = threadIdx.x & 31;
    if (wg >= BT_) return;
    const __nv_bfloat16* h = hs + (size_t)wg * H_;
    float smu = 0.0f, ssg = 0.0f;
#pragma unroll 4
    for (int k = lane * 2; k < H_; k += 64) {
        __nv_bfloat162 hh = *reinterpret_cast<const __nv_bfloat162*>(h + k);
        float h0 = __bfloat162float(hh.x), h1 = __bfloat162float(hh.y);
        smu += h0 * Wmu[k] + h1 * Wmu[k + 1];
        ssg += h0 * Wsig[k] + h1 * Wsig[k + 1];
    }
#pragma unroll
    for (int o = 16; o; o >>= 1) {
        smu += __shfl_xor_sync(0xffffffffu, smu, o);
        ssg += __shfl_xor_sync(0xffffffffu, ssg, o);
    }
    if (lane == 0) {
        out[wg] = smu + bmu[0];
        float x = ssg + bsig[0];
        out[BT_ + wg] = (x > 20.0f) ? x : log1pf(expf(x));
    }
}

// ---------------- launch ----------------
extern "C" void kernel_launch(void* const* d_in, const int* in_sizes, int n_in,
                              void* d_out, int out_size) {
    const float* x_cont = (const float*)d_in[0];
    const int*   cat0   = (const int*)  d_in[1];
    const int*   cat1   = (const int*)  d_in[2];
    const float* emb0   = (const float*)d_in[3];
    const float* emb1   = (const float*)d_in[4];
    const float* Wk1    = (const float*)d_in[5];
    const float* Wr1    = (const float*)d_in[6];
    const float* b1     = (const float*)d_in[7];
    const float* Wk2    = (const float*)d_in[8];
    const float* Wr2    = (const float*)d_in[9];
    const float* b2     = (const float*)d_in[10];
    const float* Wmu    = (const float*)d_in[11];
    const float* bmu    = (const float*)d_in[12];
    const float* Wsig   = (const float*)d_in[13];
    const float* bsig   = (const float*)d_in[14];
    float* out = (float*)d_out;

    float *px, *pwk;
    __nv_bfloat16 *pxz, *ph1, *ph2;
    unsigned* pctr;
    cudaGetSymbolAddress((void**)&px,  g_x);
    cudaGetSymbolAddress((void**)&pwk, g_wk1p);
    cudaGetSymbolAddress((void**)&pxz, g_xz);
    cudaGetSymbolAddress((void**)&ph1, g_hs1);
    cudaGetSymbolAddress((void**)&ph2, g_hs2);
    cudaGetSymbolAddress((void**)&pctr, g_ctr);

    cudaFuncSetAttribute(k_scan, cudaFuncAttributeMaxDynamicSharedMemorySize, SC_SMEM);

    dim3 gemm_grid(BT_ / 64, G4_ / 64);   // (768, 32)
    dim3 scan_grid(4, 32);                // 128 persistent CTAs

    k_init<<<1, 32>>>();
    k_build_x<<<(BT_ * DINP + 255) / 256, 256>>>(x_cont, cat0, cat1, emb0, emb1);
    k_padwk<<<(DINP * G4_ + 255) / 256, 256>>>(Wk1);

    // ---- layer 1 ----
    k_gemm<<<gemm_grid, 256>>>(px, DINP, DINP, pwk, b1, pxz);
    k_scan<<<scan_grid, 256, SC_SMEM>>>(Wr1, pxz, ph1, pctr);

    // ---- layer 2 ----
    k_gemm_b<<<gemm_grid, 256>>>(ph1, Wk2, b2, pxz);
    k_scan<<<scan_grid, 256, SC_SMEM>>>(Wr2, pxz, ph2, pctr + 4);

    // ---- heads ----
    k_heads<<<(BT_ * 32 + 255) / 256, 256>>>(ph2, Wmu, bmu, Wsig, bsig, out);
}

// round 9
// speedup vs baseline: 1.0319x; 1.0319x over previous
#include <cuda_runtime.h>
#include <cuda_bf16.h>
#include <math.h>
#include <stdint.h>

// Problem constants
#define B_    256
#define T_    192
#define F_    8
#define E0_   32
#define E1_   16
#define DINP  64          // padded input dim (real 56)
#define H_    512
#define G4_   2048
#define BT_   (B_ * T_)   // 49152
#define KC    32

// Scan smem: Bs [128][520] bf16 + As [32][520] bf16
#define NROW  520
#define SC_B_BYTES (128 * NROW * 2)       // 133120
#define SC_A_BYTES (32 * NROW * 2)        // 33280
#define SC_SMEM (SC_B_BYTES + SC_A_BYTES)

// ---------------- scratch (static device arrays; no allocation) ----------------
__device__ float g_x  [(size_t)BT_ * DINP];            // padded concat input (fp32)
__device__ float g_wk1p[DINP * G4_];                   // padded Wk1
__device__ __nv_bfloat16 g_xz [(size_t)BT_ * G4_];     // input projection (+bias), bf16
__device__ __nv_bfloat16 g_hs1[(size_t)BT_ * H_];      // layer1 hidden outputs (bf16)
__device__ __nv_bfloat16 g_hs2[(size_t)BT_ * H_];      // layer2 hidden outputs (bf16)
__device__ unsigned g_ctr[16];                         // 8 row-group barriers per layer

// ---------------- helpers ----------------
__device__ __forceinline__ unsigned f2tf(float x) {
    unsigned r;
    asm("cvt.rna.tf32.f32 %0, %1;" : "=r"(r) : "f"(x));
    return r;
}

__device__ __forceinline__ void mma8(float* c,
                                     unsigned a0, unsigned a1, unsigned a2, unsigned a3,
                                     unsigned b0, unsigned b1) {
    asm volatile(
        "mma.sync.aligned.m16n8k8.row.col.f32.tf32.tf32.f32 "
        "{%0,%1,%2,%3},{%4,%5,%6,%7},{%8,%9},{%0,%1,%2,%3};\n"
        : "+f"(c[0]), "+f"(c[1]), "+f"(c[2]), "+f"(c[3])
        : "r"(a0), "r"(a1), "r"(a2), "r"(a3), "r"(b0), "r"(b1));
}

__device__ __forceinline__ void mma16bf(float* c,
                                        unsigned a0, unsigned a1, unsigned a2, unsigned a3,
                                        unsigned b0, unsigned b1) {
    asm volatile(
        "mma.sync.aligned.m16n8k16.row.col.f32.bf16.bf16.f32 "
        "{%0,%1,%2,%3},{%4,%5,%6,%7},{%8,%9},{%0,%1,%2,%3};\n"
        : "+f"(c[0]), "+f"(c[1]), "+f"(c[2]), "+f"(c[3])
        : "r"(a0), "r"(a1), "r"(a2), "r"(a3), "r"(b0), "r"(b1));
}

__device__ __forceinline__ void ldsm4(unsigned& r0, unsigned& r1, unsigned& r2, unsigned& r3,
                                      const void* p) {
    unsigned a = (unsigned)__cvta_generic_to_shared(p);
    asm volatile("ldmatrix.sync.aligned.m8n8.x4.shared.b16 {%0,%1,%2,%3}, [%4];"
                 : "=r"(r0), "=r"(r1), "=r"(r2), "=r"(r3) : "r"(a));
}

// fast sigmoid/tanh via MUFU.EX2 path
__device__ __forceinline__ float sigm(float x) {
    float e = __expf(-x);
    return __fdividef(1.0f, 1.0f + e);
}
__device__ __forceinline__ float tanhfast(float x) {
    float e = __expf(-2.0f * x);
    return __fdividef(2.0f, 1.0f + e) - 1.0f;
}

__device__ __forceinline__ void cpa16(void* dst, const void* src) {
    unsigned d = (unsigned)__cvta_generic_to_shared(dst);
    asm volatile("cp.async.ca.shared.global [%0], [%1], 16;\n" :: "r"(d), "l"(src));
}
#define CP_COMMIT asm volatile("cp.async.commit_group;\n")
#define CP_WAIT0  asm volatile("cp.async.wait_group 0;\n")
#define CP_WAIT1  asm volatile("cp.async.wait_group 1;\n")

// ---------------- tiny kernels ----------------
__global__ void k_init() {
    if (threadIdx.x < 16) g_ctr[threadIdx.x] = 0u;
}

__global__ void k_build_x(const float* __restrict__ xc,
                          const int* __restrict__ c0, const int* __restrict__ c1,
                          const float* __restrict__ e0, const float* __restrict__ e1) {
    int i = blockIdx.x * blockDim.x + threadIdx.x;
    if (i >= BT_ * DINP) return;
    int bt = i >> 6;
    int d  = i & 63;
    float v;
    if (d < F_)                  v = xc[bt * F_ + d];
    else if (d < F_ + E0_)       v = e0[c0[bt] * E0_ + (d - F_)];
    else if (d < F_ + E0_ + E1_) v = e1[c1[bt] * E1_ + (d - F_ - E0_)];
    else                         v = 0.0f;
    g_x[i] = v;
}

__global__ void k_padwk(const float* __restrict__ Wk1) {
    int i = blockIdx.x * blockDim.x + threadIdx.x;
    if (i >= DINP * G4_) return;
    int r = i >> 11, c = i & 2047;
    g_wk1p[i] = (r < 56) ? Wk1[r * G4_ + c] : 0.0f;
}

// ---------------- TF32 GEMM (fp32 A): C[M,2048] = A[M,K] @ W[K,2048] + bias (bf16 out) ----------------
__global__ void __launch_bounds__(256)
k_gemm(const float* __restrict__ A, int lda, int K,
       const float* __restrict__ W, const float* __restrict__ bias,
       __nv_bfloat16* __restrict__ C) {
    __shared__ float As[2][64][36];
    __shared__ float Bs[2][32][72];
    int m0 = blockIdx.x * 64, n0 = blockIdx.y * 64;
    int tid = threadIdx.x;
    int lane = tid & 31, warp = tid >> 5;
    int wm = warp >> 1, wn = warp & 1;
    int g = lane >> 2, tg = lane & 3;

    float acc[4][4];
#pragma unroll
    for (int i = 0; i < 4; i++)
#pragma unroll
        for (int j = 0; j < 4; j++) acc[i][j] = 0.0f;

    int nch = K / KC;
    {
#pragma unroll
        for (int ii = 0; ii < 2; ii++) {
            int idx = tid + 256 * ii;
            int r = idx >> 3, q = idx & 7;
            cpa16(&As[0][r][q * 4], &A[(size_t)(m0 + r) * lda + q * 4]);
        }
#pragma unroll
        for (int ii = 0; ii < 2; ii++) {
            int idx = tid + 256 * ii;
            int k = idx >> 4, q = idx & 15;
            cpa16(&Bs[0][k][q * 4], &W[(size_t)k * G4_ + n0 + q * 4]);
        }
        CP_COMMIT;
    }

    for (int kc = 0; kc < nch; kc++) {
        int b = kc & 1;
        if (kc + 1 < nch) {
            int b2 = b ^ 1;
            int k0 = (kc + 1) * KC;
#pragma unroll
            for (int ii = 0; ii < 2; ii++) {
                int idx = tid + 256 * ii;
                int r = idx >> 3, q = idx & 7;
                cpa16(&As[b2][r][q * 4], &A[(size_t)(m0 + r) * lda + k0 + q * 4]);
            }
#pragma unroll
            for (int ii = 0; ii < 2; ii++) {
                int idx = tid + 256 * ii;
                int k = idx >> 4, q = idx & 15;
                cpa16(&Bs[b2][k][q * 4], &W[(size_t)(k0 + k) * G4_ + n0 + q * 4]);
            }
            CP_COMMIT;
            CP_WAIT1;
        } else {
            CP_WAIT0;
        }
        __syncthreads();
#pragma unroll
        for (int ks = 0; ks < KC; ks += 8) {
            unsigned a0 = f2tf(As[b][wm * 16 + g][ks + tg]);
            unsigned a1 = f2tf(As[b][wm * 16 + g + 8][ks + tg]);
            unsigned a2 = f2tf(As[b][wm * 16 + g][ks + tg + 4]);
            unsigned a3 = f2tf(As[b][wm * 16 + g + 8][ks + tg + 4]);
#pragma unroll
            for (int nt = 0; nt < 4; nt++) {
                unsigned b0 = f2tf(Bs[b][ks + tg][wn * 32 + nt * 8 + g]);
                unsigned b1 = f2tf(Bs[b][ks + tg + 4][wn * 32 + nt * 8 + g]);
                mma8(acc[nt], a0, a1, a2, a3, b0, b1);
            }
        }
        __syncthreads();
    }

    int rl = wm * 16 + g;
#pragma unroll
    for (int nt = 0; nt < 4; nt++) {
        int cl  = wn * 32 + nt * 8 + tg * 2;
        int col = n0 + cl;
        float bb0 = bias[col], bb1 = bias[col + 1];
        size_t o0 = (size_t)(m0 + rl) * G4_ + col;
        size_t o1 = (size_t)(m0 + rl + 8) * G4_ + col;
        __nv_bfloat162 p0 = __floats2bfloat162_rn(acc[nt][0] + bb0, acc[nt][1] + bb1);
        __nv_bfloat162 p1 = __floats2bfloat162_rn(acc[nt][2] + bb0, acc[nt][3] + bb1);
        *reinterpret_cast<__nv_bfloat162*>(C + o0) = p0;
        *reinterpret_cast<__nv_bfloat162*>(C + o1) = p1;
    }
}

// ---------------- TF32 GEMM with bf16 A (layer-2 input projection), K=512, bf16 out ----------------
__global__ void __launch_bounds__(256)
k_gemm_b(const __nv_bfloat16* __restrict__ A,
         const float* __restrict__ W, const float* __restrict__ bias,
         __nv_bfloat16* __restrict__ C) {
    __shared__ __nv_bfloat16 As[2][64][40];
    __shared__ float Bs[2][32][72];
    int m0 = blockIdx.x * 64, n0 = blockIdx.y * 64;
    int tid = threadIdx.x;
    int lane = tid & 31, warp = tid >> 5;
    int wm = warp >> 1, wn = warp & 1;
    int g = lane >> 2, tg = lane & 3;

    float acc[4][4];
#pragma unroll
    for (int i = 0; i < 4; i++)
#pragma unroll
        for (int j = 0; j < 4; j++) acc[i][j] = 0.0f;

    {
        int r = tid >> 2, q = tid & 3;
        cpa16(&As[0][r][q * 8], &A[(size_t)(m0 + r) * H_ + q * 8]);
#pragma unroll
        for (int ii = 0; ii < 2; ii++) {
            int idx = tid + 256 * ii;
            int k = idx >> 4, qq = idx & 15;
            cpa16(&Bs[0][k][qq * 4], &W[(size_t)k * G4_ + n0 + qq * 4]);
        }
        CP_COMMIT;
    }

    for (int kc = 0; kc < 16; kc++) {
        int b = kc & 1;
        if (kc < 15) {
            int b2 = b ^ 1;
            int k0 = (kc + 1) * KC;
            int r = tid >> 2, q = tid & 3;
            cpa16(&As[b2][r][q * 8], &A[(size_t)(m0 + r) * H_ + k0 + q * 8]);
#pragma unroll
            for (int ii = 0; ii < 2; ii++) {
                int idx = tid + 256 * ii;
                int k = idx >> 4, qq = idx & 15;
                cpa16(&Bs[b2][k][qq * 4], &W[(size_t)(k0 + k) * G4_ + n0 + qq * 4]);
            }
            CP_COMMIT;
            CP_WAIT1;
        } else {
            CP_WAIT0;
        }
        __syncthreads();
#pragma unroll
        for (int ks = 0; ks < KC; ks += 8) {
            unsigned a0 = __float_as_uint(__bfloat162float(As[b][wm * 16 + g][ks + tg]));
            unsigned a1 = __float_as_uint(__bfloat162float(As[b][wm * 16 + g + 8][ks + tg]));
            unsigned a2 = __float_as_uint(__bfloat162float(As[b][wm * 16 + g][ks + tg + 4]));
            unsigned a3 = __float_as_uint(__bfloat162float(As[b][wm * 16 + g + 8][ks + tg + 4]));
#pragma unroll
            for (int nt = 0; nt < 4; nt++) {
                unsigned b0 = f2tf(Bs[b][ks + tg][wn * 32 + nt * 8 + g]);
                unsigned b1 = f2tf(Bs[b][ks + tg + 4][wn * 32 + nt * 8 + g]);
                mma8(acc[nt], a0, a1, a2, a3, b0, b1);
            }
        }
        __syncthreads();
    }

    int rl = wm * 16 + g;
#pragma unroll
    for (int nt = 0; nt < 4; nt++) {
        int cl  = wn * 32 + nt * 8 + tg * 2;
        int col = n0 + cl;
        float bb0 = bias[col], bb1 = bias[col + 1];
        size_t o0 = (size_t)(m0 + rl) * G4_ + col;
        size_t o1 = (size_t)(m0 + rl + 8) * G4_ + col;
        __nv_bfloat162 p0 = __floats2bfloat162_rn(acc[nt][0] + bb0, acc[nt][1] + bb1);
        __nv_bfloat162 p1 = __floats2bfloat162_rn(acc[nt][2] + bb0, acc[nt][3] + bb1);
        *reinterpret_cast<__nv_bfloat162*>(C + o0) = p0;
        *reinterpret_cast<__nv_bfloat162*>(C + o1) = p1;
    }
}

// ---------------- persistent bf16 LSTM scan ----------------
// grid (8, 16), 256 threads. CTA: 32 batch rows x 128 z-cols (32 j x 4 gates).
// Bs [128 ns][512 k]: ns = wn*32 + gate*8 + jj maps warp wn's 4 acc n8-blocks to
// the 4 gates of the same 8 j's -> register-only cell update.
// A-tile halved to 32KB/step; barrier groups of 16 CTAs.
__global__ void __launch_bounds__(256)
k_scan(const float* __restrict__ Wr, const __nv_bfloat16* __restrict__ xz,
       __nv_bfloat16* __restrict__ hs, unsigned* __restrict__ ctr) {
    extern __shared__ char smem[];
    __nv_bfloat16* Bsm = reinterpret_cast<__nv_bfloat16*>(smem);
    __nv_bfloat16* Asm = reinterpret_cast<__nv_bfloat16*>(smem + SC_B_BYTES);

    int m0 = blockIdx.x * 32;          // 8 row groups of 32
    int j0 = blockIdx.y * 32;          // 16 j groups of 32
    int gidx = blockIdx.x;
    int tid = threadIdx.x;
    int lane = tid & 31, warp = tid >> 5;
    int wm = warp >> 2, wn = warp & 3; // 2 row-tiles x 4 n-tiles
    int g = lane >> 2, tg = lane & 3;

    // preload Wr slice: ns = wn32*32? -> row ns holds column gate*512 + j0 + j
    // ns decomposition: block = ns>>5 (0..3 = wn), gate = (ns>>3)&3, jj = ns&7
    // j = (ns>>5)*8 + jj
    for (int i = tid; i < 128 * 512; i += 256) {
        int ns = i & 127, k = i >> 7;
        int col = ((ns >> 3) & 3) * 512 + j0 + ((ns >> 5) << 3) + (ns & 7);
        Bsm[ns * NROW + k] = __float2bfloat16(Wr[(size_t)k * G4_ + col]);
    }
    __syncthreads();

    // fragment addressing
    int a_row  = wm * 16 + (lane & 7) + ((lane >> 3) & 1) * 8;   // 0..31
    int a_koff = ((lane >> 4) & 1) * 8;
    int b_nl0  = wn * 32 + ((lane >> 4) & 1) * 8 + (lane & 7);
    int b_koff = ((lane >> 3) & 1) * 8;
    int jloc   = wn * 8 + tg * 2;           // this thread's 2 j's within 32
    int r0     = m0 + wm * 16 + g;          // rows r0, r0+8

    float creg[4] = {0.0f, 0.0f, 0.0f, 0.0f};
    float xf[2][4][2];

    // prologue: xz for t=0
#pragma unroll
    for (int rr = 0; rr < 2; rr++) {
        const __nv_bfloat16* xp = xz + ((size_t)(r0 + rr * 8) * T_) * G4_ + j0 + jloc;
#pragma unroll
        for (int gate = 0; gate < 4; gate++) {
            __nv_bfloat162 w = *reinterpret_cast<const __nv_bfloat162*>(xp + gate * 512);
            xf[rr][gate][0] = __bfloat162float(w.x);
            xf[rr][gate][1] = __bfloat162float(w.y);
        }
    }

    for (int t = 0; t < T_; t++) {
        // stage h[t-1] (32 rows x 512 k bf16 = 32KB): two commit groups
        if (t > 0) {
#pragma unroll
            for (int ii = 0; ii < 4; ii++) {
                int idx = tid + 256 * ii;       // 1024 quads (k 0..255)
                int r = idx >> 5, q8 = idx & 31;
                cpa16(&Asm[r * NROW + q8 * 8],
                      &hs[((size_t)(m0 + r) * T_ + (t - 1)) * H_ + q8 * 8]);
            }
            CP_COMMIT;
#pragma unroll
            for (int ii = 0; ii < 4; ii++) {
                int idx = tid + 256 * ii;       // k 256..511
                int r = idx >> 5, q8 = (idx & 31) + 32;
                cpa16(&Asm[r * NROW + q8 * 8],
                      &hs[((size_t)(m0 + r) * T_ + (t - 1)) * H_ + q8 * 8]);
            }
            CP_COMMIT;
        }

        float acc[4][4];
#pragma unroll
        for (int i = 0; i < 4; i++)
#pragma unroll
            for (int j = 0; j < 4; j++) acc[i][j] = 0.0f;

        if (t > 0) {
            CP_WAIT1;
            __syncthreads();
#pragma unroll 4
            for (int ks = 0; ks < 16; ks++) {
                unsigned a0, a1, a2, a3;
                ldsm4(a0, a1, a2, a3, &Asm[a_row * NROW + ks * 16 + a_koff]);
                unsigned c0, c1, c2, c3;
                ldsm4(c0, c1, c2, c3, &Bsm[b_nl0 * NROW + ks * 16 + b_koff]);
                mma16bf(acc[0], a0, a1, a2, a3, c0, c1);
                mma16bf(acc[1], a0, a1, a2, a3, c2, c3);
                ldsm4(c0, c1, c2, c3, &Bsm[(b_nl0 + 16) * NROW + ks * 16 + b_koff]);
                mma16bf(acc[2], a0, a1, a2, a3, c0, c1);
                mma16bf(acc[3], a0, a1, a2, a3, c2, c3);
            }
            CP_WAIT0;
            __syncthreads();
#pragma unroll 4
            for (int ks = 16; ks < 32; ks++) {
                unsigned a0, a1, a2, a3;
                ldsm4(a0, a1, a2, a3, &Asm[a_row * NROW + ks * 16 + a_koff]);
                unsigned c0, c1, c2, c3;
                ldsm4(c0, c1, c2, c3, &Bsm[b_nl0 * NROW + ks * 16 + b_koff]);
                mma16bf(acc[0], a0, a1, a2, a3, c0, c1);
                mma16bf(acc[1], a0, a1, a2, a3, c2, c3);
                ldsm4(c0, c1, c2, c3, &Bsm[(b_nl0 + 16) * NROW + ks * 16 + b_koff]);
                mma16bf(acc[2], a0, a1, a2, a3, c0, c1);
                mma16bf(acc[3], a0, a1, a2, a3, c2, c3);
            }
        }

        // fused cell update, fully in registers (acc blocks = gates i,f,g,o)
#pragma unroll
        for (int rr = 0; rr < 2; rr++) {
            float hv[2];
#pragma unroll
            for (int jj = 0; jj < 2; jj++) {
                int q = rr * 2 + jj;
                float zi = acc[0][q] + xf[rr][0][jj];
                float zf = acc[1][q] + xf[rr][1][jj];
                float zg = acc[2][q] + xf[rr][2][jj];
                float zo = acc[3][q] + xf[rr][3][jj];
                float iv = sigm(zi);
                float fv = sigm(zf);
                float gv = tanhfast(zg);
                float ov = sigm(zo);
                float cv = fv * creg[q] + iv * gv;
                creg[q] = cv;
                hv[jj] = ov * tanhfast(cv);
            }
            *reinterpret_cast<__nv_bfloat162*>(
                hs + ((size_t)(r0 + rr * 8) * T_ + t) * H_ + j0 + jloc) =
                __floats2bfloat162_rn(hv[0], hv[1]);
        }

        // group barrier: release-scoped arrive by tid0 (after cta barrier)
        __syncthreads();
        if (tid == 0)
            asm volatile("red.release.gpu.global.add.u32 [%0], %1;"
                         :: "l"(ctr + gidx), "r"(1u) : "memory");

        // prefetch next step's xz while others arrive
        if (t + 1 < T_) {
#pragma unroll
            for (int rr = 0; rr < 2; rr++) {
                const __nv_bfloat16* xp =
                    xz + ((size_t)(r0 + rr * 8) * T_ + (t + 1)) * G4_ + j0 + jloc;
#pragma unroll
                for (int gate = 0; gate < 4; gate++) {
                    __nv_bfloat162 w = *reinterpret_cast<const __nv_bfloat162*>(xp + gate * 512);
                    xf[rr][gate][0] = __bfloat162float(w.x);
                    xf[rr][gate][1] = __bfloat162float(w.y);
                }
            }
        }

        if (tid == 0) {
            unsigned tgt = 16u * (unsigned)(t + 1);
            unsigned v;
            do {
                asm volatile("ld.acquire.gpu.u32 %0, [%1];" : "=r"(v) : "l"(ctr + gidx));
            } while (v < tgt);
        }
        __syncthreads();
    }
}

// ---------------- output heads: mu, softplus(sigma) (bf16 hs) ----------------
__global__ void k_heads(const __nv_bfloat16* __restrict__ hs,
                        const float* __restrict__ Wmu, const float* __restrict__ bmu,
                        const float* __restrict__ Wsig, const float* __restrict__ bsig,
                        float* __restrict__ out) {
    int wg  = (blockIdx.x * blockDim.x + threadIdx.x) >> 5;
    int lane = threadIdx.x & 31;
    if (wg >= BT_) return;
    const __nv_bfloat16* h = hs + (size_t)wg * H_;
    float smu = 0.0f, ssg = 0.0f;
#pragma unroll 4
    for (int k = lane * 2; k < H_; k += 64) {
        __nv_bfloat162 hh = *reinterpret_cast<const __nv_bfloat162*>(h + k);
        float h0 = __bfloat162float(hh.x), h1 = __bfloat162float(hh.y);
        smu += h0 * Wmu[k] + h1 * Wmu[k + 1];
        ssg += h0 * Wsig[k] + h1 * Wsig[k + 1];
    }
#pragma unroll
    for (int o = 16; o; o >>= 1) {
        smu += __shfl_xor_sync(0xffffffffu, smu, o);
        ssg += __shfl_xor_sync(0xffffffffu, ssg, o);
    }
    if (lane == 0) {
        out[wg] = smu + bmu[0];
        float x = ssg + bsig[0];
        out[BT_ + wg] = (x > 20.0f) ? x : log1pf(expf(x));
    }
}

// ---------------- launch ----------------
extern "C" void kernel_launch(void* const* d_in, const int* in_sizes, int n_in,
                              void* d_out, int out_size) {
    const float* x_cont = (const float*)d_in[0];
    const int*   cat0   = (const int*)  d_in[1];
    const int*   cat1   = (const int*)  d_in[2];
    const float* emb0   = (const float*)d_in[3];
    const float* emb1   = (const float*)d_in[4];
    const float* Wk1    = (const float*)d_in[5];
    const float* Wr1    = (const float*)d_in[6];
    const float* b1     = (const float*)d_in[7];
    const float* Wk2    = (const float*)d_in[8];
    const float* Wr2    = (const float*)d_in[9];
    const float* b2     = (const float*)d_in[10];
    const float* Wmu    = (const float*)d_in[11];
    const float* bmu    = (const float*)d_in[12];
    const float* Wsig   = (const float*)d_in[13];
    const float* bsig   = (const float*)d_in[14];
    float* out = (float*)d_out;

    float *px, *pwk;
    __nv_bfloat16 *pxz, *ph1, *ph2;
    unsigned* pctr;
    cudaGetSymbolAddress((void**)&px,  g_x);
    cudaGetSymbolAddress((void**)&pwk, g_wk1p);
    cudaGetSymbolAddress((void**)&pxz, g_xz);
    cudaGetSymbolAddress((void**)&ph1, g_hs1);
    cudaGetSymbolAddress((void**)&ph2, g_hs2);
    cudaGetSymbolAddress((void**)&pctr, g_ctr);

    cudaFuncSetAttribute(k_scan, cudaFuncAttributeMaxDynamicSharedMemorySize, SC_SMEM);

    dim3 gemm_grid(BT_ / 64, G4_ / 64);   // (768, 32)
    dim3 scan_grid(8, 16);                // 128 persistent CTAs

    k_init<<<1, 32>>>();
    k_build_x<<<(BT_ * DINP + 255) / 256, 256>>>(x_cont, cat0, cat1, emb0, emb1);
    k_padwk<<<(DINP * G4_ + 255) / 256, 256>>>(Wk1);

    // ---- layer 1 ----
    k_gemm<<<gemm_grid, 256>>>(px, DINP, DINP, pwk, b1, pxz);
    k_scan<<<scan_grid, 256, SC_SMEM>>>(Wr1, pxz, ph1, pctr);

    // ---- layer 2 ----
    k_gemm_b<<<gemm_grid, 256>>>(ph1, Wk2, b2, pxz);
    k_scan<<<scan_grid, 256, SC_SMEM>>>(Wr2, pxz, ph2, pctr + 8);

    // ---- heads ----
    k_heads<<<(BT_ * 32 + 255) / 256, 256>>>(ph2, Wmu, bmu, Wsig, bsig, out);
}